// round 2
// baseline (speedup 1.0000x reference)
#include <cuda_runtime.h>
#include <cstdint>
#include <cstddef>

// TensorFusion: out = tanh(tanh(tanh(F@W1+b1)@W2+b2)@W3+b3)
// F[b, (i,j,k)] = a_h[b,i]*v_h[b,j]*t_h[b,k]  (rank-1 structured, never materialized)
//
// Kernel 1: for each ij block (65 W1 rows), compute u[b,h] = sum_k t_h[b,k]*W1[ij*65+k,h],
//           then acc[b,h] += (a_h[b,i]*v_h[b,j]) * u[b,h].  Split-K over 37 ij-chunks,
//           partials to __device__ scratch.  fp32 via packed fma.rn.f32x2 (2x FFMA rate on sm_103a).
// Kernel 2: reduce 37 partials + bias + tanh, then two 64x64 GEMMs + tanh.

#define NSPLIT 37
#define IJ_TOTAL 4225   // 65*65

typedef unsigned long long ull;

__device__ float g_partial[NSPLIT * 512 * 64];

__device__ __forceinline__ ull ffma2(ull a, ull b, ull c) {
    ull d;
    asm("fma.rn.f32x2 %0, %1, %2, %3;" : "=l"(d) : "l"(a), "l"(b), "l"(c));
    return d;
}
__device__ __forceinline__ ull pk2(float x) {
    ull d;
    asm("mov.b64 %0, {%1, %1};" : "=l"(d) : "f"(x));
    return d;
}

__global__ __launch_bounds__(256, 1)
void fusion_kernel(const float* __restrict__ l, const float* __restrict__ a,
                   const float* __restrict__ v, const float* __restrict__ W1) {
    __shared__ __align__(16) float t_s[128 * 65];   // t_h tile for this 128-row b-tile
    __shared__ __align__(16) float w_s[33 * 64];    // half of one W1 ij-block (65 rows split 33+32)

    const int tid   = threadIdx.x;
    const int btile = blockIdx.x;     // 0..3  (128 b-rows each)
    const int split = blockIdx.y;     // 0..NSPLIT-1
    const int b0    = btile * 128;

    // Load t_h tile (homogeneous: col 0 = 1, cols 1..64 = l)
    for (int x = tid; x < 128 * 65; x += 256) {
        int b = x / 65;
        int k = x - b * 65;
        t_s[x] = (k == 0) ? 1.0f : l[(b0 + b) * 64 + (k - 1)];
    }

    const int hg = tid & 7;           // 8 h-groups of 8 cols
    const int bg = tid >> 3;          // 32 b-groups of 4 rows
    const int h0 = hg * 8;

    ull acc[4][4];                    // persistent [4 b][4 f32x2-pairs over 8 h]
    #pragma unroll
    for (int bb = 0; bb < 4; ++bb)
        #pragma unroll
        for (int hp = 0; hp < 4; ++hp) acc[bb][hp] = 0ULL;

    const int ij_s = (split * IJ_TOTAL) / NSPLIT;
    const int ij_e = ((split + 1) * IJ_TOTAL) / NSPLIT;

    // Preload first W phase into registers (pipelined staging: LDG -> regs -> STS)
    float4 r[3];
    {
        const float4* wg = (const float4*)(W1 + (size_t)ij_s * 4160);
        #pragma unroll
        for (int c = 0; c < 3; ++c) {
            int x = c * 256 + tid;
            if (x < 33 * 16) r[c] = __ldg(&wg[x]);
        }
    }
    __syncthreads();

    for (int ij = ij_s; ij < ij_e; ++ij) {
        const int i = ij / 65;
        const int j = ij - i * 65;

        // prefetch a_h/v_h scalars for this block's epilogue (hidden behind k-loops)
        float av[4], vv[4];
        #pragma unroll
        for (int bb = 0; bb < 4; ++bb) {
            int b = b0 + bg * 4 + bb;
            av[bb] = (i == 0) ? 1.0f : __ldg(&a[b * 64 + (i - 1)]);
            vv[bb] = (j == 0) ? 1.0f : __ldg(&v[b * 64 + (j - 1)]);
        }

        ull u[4][4];
        #pragma unroll
        for (int bb = 0; bb < 4; ++bb)
            #pragma unroll
            for (int hp = 0; hp < 4; ++hp) u[bb][hp] = 0ULL;

        #pragma unroll
        for (int ph = 0; ph < 2; ++ph) {
            const int k0 = ph ? 33 : 0;
            const int kn = ph ? 32 : 33;

            __syncthreads();               // previous phase readers done
            #pragma unroll
            for (int c = 0; c < 3; ++c) {
                int x = c * 256 + tid;
                if (x < kn * 16) ((float4*)w_s)[x] = r[c];
            }
            __syncthreads();               // w_s visible

            // preload next phase's W chunk into regs (hides LDG behind k-loop)
            {
                int nij = ij, nk0 = 33, nkn = 32;
                if (ph == 1) { nij = ij + 1; nk0 = 0; nkn = 33; }
                if (nij < ij_e) {
                    const float4* wg = (const float4*)(W1 + (size_t)nij * 4160) + nk0 * 16;
                    #pragma unroll
                    for (int c = 0; c < 3; ++c) {
                        int x = c * 256 + tid;
                        if (x < nkn * 16) r[c] = __ldg(&wg[x]);
                    }
                }
            }

            const float* ts = t_s + bg * 4 * 65 + k0;
            #pragma unroll 4
            for (int k = 0; k < kn; ++k) {
                ulonglong2 wA = *reinterpret_cast<const ulonglong2*>(&w_s[k * 64 + h0]);
                ulonglong2 wB = *reinterpret_cast<const ulonglong2*>(&w_s[k * 64 + h0 + 4]);
                #pragma unroll
                for (int bb = 0; bb < 4; ++bb) {
                    ull tp = pk2(ts[bb * 65 + k]);
                    u[bb][0] = ffma2(tp, wA.x, u[bb][0]);
                    u[bb][1] = ffma2(tp, wA.y, u[bb][1]);
                    u[bb][2] = ffma2(tp, wB.x, u[bb][2]);
                    u[bb][3] = ffma2(tp, wB.y, u[bb][3]);
                }
            }
        }

        // epilogue: scale by P[b,ij] = a_h[b,i]*v_h[b,j], accumulate
        #pragma unroll
        for (int bb = 0; bb < 4; ++bb) {
            ull pp = pk2(av[bb] * vv[bb]);
            #pragma unroll
            for (int hp = 0; hp < 4; ++hp)
                acc[bb][hp] = ffma2(pp, u[bb][hp], acc[bb][hp]);
        }
    }

    // write split-K partial
    float* dst = g_partial + (size_t)split * (512 * 64);
    #pragma unroll
    for (int bb = 0; bb < 4; ++bb) {
        int b = b0 + bg * 4 + bb;
        #pragma unroll
        for (int hp = 0; hp < 4; ++hp)
            *reinterpret_cast<ull*>(&dst[b * 64 + h0 + hp * 2]) = acc[bb][hp];
    }
}

__global__ __launch_bounds__(256, 1)
void mlp_kernel(const float* __restrict__ b1, const float* __restrict__ W2,
                const float* __restrict__ b2, const float* __restrict__ W3,
                const float* __restrict__ b3, float* __restrict__ out) {
    __shared__ __align__(16) float h_s[64 * 65];   // padded [64 b][64 h]
    __shared__ __align__(16) float w_s[64 * 64];

    const int tid = threadIdx.x;
    const int bt  = blockIdx.x;      // 0..7, 64 b-rows each

    // Phase 0: reduce split-K partials + b1 + tanh -> h1 (coalesced linear mapping)
    #pragma unroll 4
    for (int c = 0; c < 16; ++c) {
        int idx = c * 256 + tid;             // 0..4095 within this b-tile
        int off = bt * 4096 + idx;
        float s = 0.0f;
        #pragma unroll
        for (int rsp = 0; rsp < NSPLIT; ++rsp)
            s += g_partial[(size_t)rsp * (512 * 64) + off];
        int b = idx >> 6, h = idx & 63;
        h_s[b * 65 + h] = tanhf(s + b1[h]);
    }
    for (int x = tid; x < 1024; x += 256)
        ((float4*)w_s)[x] = ((const float4*)W2)[x];
    __syncthreads();

    const int hg = tid & 7, bg = tid >> 3;
    const int h0 = hg * 8;

    // Layer 2: h2 = tanh(h1 @ W2 + b2)
    float acc[2][8];
    #pragma unroll
    for (int bb = 0; bb < 2; ++bb)
        #pragma unroll
        for (int hh = 0; hh < 8; ++hh) acc[bb][hh] = 0.0f;

    #pragma unroll 4
    for (int k = 0; k < 64; ++k) {
        float hv0 = h_s[(bg * 2 + 0) * 65 + k];
        float hv1 = h_s[(bg * 2 + 1) * 65 + k];
        const float* wr = &w_s[k * 64 + h0];
        #pragma unroll
        for (int hh = 0; hh < 8; ++hh) {
            float wv = wr[hh];
            acc[0][hh] += hv0 * wv;
            acc[1][hh] += hv1 * wv;
        }
    }
    __syncthreads();
    #pragma unroll
    for (int bb = 0; bb < 2; ++bb)
        #pragma unroll
        for (int hh = 0; hh < 8; ++hh)
            h_s[(bg * 2 + bb) * 65 + h0 + hh] = tanhf(acc[bb][hh] + b2[h0 + hh]);
    for (int x = tid; x < 1024; x += 256)
        ((float4*)w_s)[x] = ((const float4*)W3)[x];
    __syncthreads();

    // Layer 3: out = tanh(h2 @ W3 + b3)
    #pragma unroll
    for (int bb = 0; bb < 2; ++bb)
        #pragma unroll
        for (int hh = 0; hh < 8; ++hh) acc[bb][hh] = 0.0f;

    #pragma unroll 4
    for (int k = 0; k < 64; ++k) {
        float hv0 = h_s[(bg * 2 + 0) * 65 + k];
        float hv1 = h_s[(bg * 2 + 1) * 65 + k];
        const float* wr = &w_s[k * 64 + h0];
        #pragma unroll
        for (int hh = 0; hh < 8; ++hh) {
            float wv = wr[hh];
            acc[0][hh] += hv0 * wv;
            acc[1][hh] += hv1 * wv;
        }
    }

    #pragma unroll
    for (int bb = 0; bb < 2; ++bb) {
        int b = bt * 64 + bg * 2 + bb;
        float o[8];
        #pragma unroll
        for (int hh = 0; hh < 8; ++hh)
            o[hh] = tanhf(acc[bb][hh] + b3[h0 + hh]);
        float4 o0 = make_float4(o[0], o[1], o[2], o[3]);
        float4 o1 = make_float4(o[4], o[5], o[6], o[7]);
        *reinterpret_cast<float4*>(&out[b * 64 + h0])     = o0;
        *reinterpret_cast<float4*>(&out[b * 64 + h0 + 4]) = o1;
    }
}

extern "C" void kernel_launch(void* const* d_in, const int* in_sizes, int n_in,
                              void* d_out, int out_size) {
    (void)in_sizes; (void)n_in; (void)out_size;
    const float* l  = (const float*)d_in[0];
    const float* a  = (const float*)d_in[1];
    const float* v  = (const float*)d_in[2];
    const float* W1 = (const float*)d_in[3];
    const float* b1 = (const float*)d_in[4];
    const float* W2 = (const float*)d_in[5];
    const float* b2 = (const float*)d_in[6];
    const float* W3 = (const float*)d_in[7];
    const float* b3 = (const float*)d_in[8];
    float* out = (float*)d_out;

    dim3 grid1(4, NSPLIT);
    fusion_kernel<<<grid1, 256>>>(l, a, v, W1);
    mlp_kernel<<<8, 256>>>(b1, W2, b2, W3, b3, out);
}

// round 6
// speedup vs baseline: 2.7319x; 2.7319x over previous
#include <cuda_runtime.h>
#include <cstdint>
#include <cstddef>

// TensorFusion via portable mma.sync (HMMA bf16) — compute_103-safe (no tcgen05).
// out1[b,h] = sum_i a_h[b,i] * (G[b,:] @ W1_i),  G[b,jk] = v_h[b,j]*t_h[b,k]
// Split-bf16 (hi/lo), 3 cross-terms: GhWh + GhWl + GlWh  (error ~2^-17).
// Grid 4 btiles x 34 jk-splits = 136 CTAs. G resident in smem; W double-buffered.

#define NSPLIT 34
#define JK_TOTAL 4225
#define NI 65

__device__ float g_partial[NSPLIT * 512 * 64];
__device__ float g_h1[512 * 64];

// ---------- helpers ----------
__device__ __forceinline__ uint32_t smem_u32(const void* p) {
    uint32_t r;
    asm("{ .reg .u64 t; cvta.to.shared.u64 t, %1; cvt.u32.u64 %0, t; }" : "=r"(r) : "l"(p));
    return r;
}
// res.lo = a, res.hi = b
#define CVT_BF16X2(res, a, b) \
    asm("cvt.rn.satfinite.bf16x2.f32 %0, %1, %2;" : "=r"(res) : "f"(b), "f"(a))

#define LDSM4(R, ADDR) \
    asm volatile("ldmatrix.sync.aligned.m8n8.x4.shared.b16 {%0,%1,%2,%3}, [%4];" \
                 : "=r"((R)[0]), "=r"((R)[1]), "=r"((R)[2]), "=r"((R)[3]) : "r"(ADDR))
#define LDSM4T(R, ADDR) \
    asm volatile("ldmatrix.sync.aligned.m8n8.x4.trans.shared.b16 {%0,%1,%2,%3}, [%4];" \
                 : "=r"((R)[0]), "=r"((R)[1]), "=r"((R)[2]), "=r"((R)[3]) : "r"(ADDR))
#define MMA_BF16(D, A, B0, B1) \
    asm volatile("mma.sync.aligned.m16n8k16.row.col.f32.bf16.bf16.f32 " \
                 "{%0,%1,%2,%3}, {%4,%5,%6,%7}, {%8,%9}, {%0,%1,%2,%3};" \
                 : "+f"((D)[0]), "+f"((D)[1]), "+f"((D)[2]), "+f"((D)[3]) \
                 : "r"((A)[0]), "r"((A)[1]), "r"((A)[2]), "r"((A)[3]), "r"(B0), "r"(B1))

// ---------- smem layout ----------
// W buffers: [buf][hi/lo] each [128 rows(k)][72 cols(h) bf16]  (stride 144B: conflict-free)
// G tiles:   hi/lo each [128 rows(b)][136 cols(jk) bf16]       (stride 272B: conflict-free)
// a_s:       [128 rows(b)][65 i] f32
#define W_STRIDE 72
#define W_BYTES  (128 * W_STRIDE * 2)       // 18432
#define SM_WBUF  0                          // hi0, lo0, hi1, lo1 -> 73728
#define G_STRIDE 136
#define SM_GHI   73728
#define SM_GLO   (SM_GHI + 128 * G_STRIDE * 2)   // +34816 = 108544
#define SM_AS    (SM_GLO + 128 * G_STRIDE * 2)   // 143360
#define SMEM_TOTAL (SM_AS + 128 * 65 * 4)        // 176640

__global__ __launch_bounds__(256, 1)
void fusion_mma_kernel(const float* __restrict__ l, const float* __restrict__ a,
                       const float* __restrict__ v, const float* __restrict__ W1) {
    extern __shared__ __align__(1024) char smem[];
    const uint32_t sb = smem_u32(smem);
    const int tid  = threadIdx.x;
    const int warp = tid >> 5;
    const int lane = tid & 31;
    const int b0   = blockIdx.x * 128;
    const int jk0  = blockIdx.y * 128;

    float* a_s = (float*)(smem + SM_AS);

    // ---- stage a_s[128][65] ----
    for (int x = tid; x < 128 * 65; x += 256) {
        int r = x / 65, i = x - r * 65;
        a_s[x] = (i == 0) ? 1.0f : __ldg(&a[(b0 + r) * 64 + (i - 1)]);
    }

    // ---- build G tile (hi/lo bf16) ----
    {
        int r  = tid >> 1;
        int c0 = (tid & 1) * 64;
        const float* lrow = l + (size_t)(b0 + r) * 64;
        const float* vrow = v + (size_t)(b0 + r) * 64;
        int jk = jk0 + c0;
        int j  = jk / 65, k = jk - j * 65;
        uint32_t ghbase = sb + SM_GHI + (uint32_t)(r * G_STRIDE + c0) * 2;
        uint32_t glbase = sb + SM_GLO + (uint32_t)(r * G_STRIDE + c0) * 2;
        for (int c = 0; c < 64; c += 2) {
            float g0 = 0.0f, g1 = 0.0f;
            if (jk < JK_TOTAL)
                g0 = (j ? __ldg(&vrow[j - 1]) : 1.0f) * (k ? __ldg(&lrow[k - 1]) : 1.0f);
            ++jk; if (++k == 65) { k = 0; ++j; }
            if (jk < JK_TOTAL)
                g1 = (j ? __ldg(&vrow[j - 1]) : 1.0f) * (k ? __ldg(&lrow[k - 1]) : 1.0f);
            ++jk; if (++k == 65) { k = 0; ++j; }
            uint32_t hp; CVT_BF16X2(hp, g0, g1);
            float e0 = g0 - __uint_as_float(hp << 16);
            float e1 = g1 - __uint_as_float(hp & 0xFFFF0000u);
            uint32_t lp; CVT_BF16X2(lp, e0, e1);
            *(uint32_t*)(smem + (ghbase - sb) + c * 2) = hp;
            *(uint32_t*)(smem + (glbase - sb) + c * 2) = lp;
        }
    }

    // ---- W stage helpers (inline) ----
    // thread t: row r = t>>1 (k dim), cols (t&1)*32 .. +32
    const int wr_row = tid >> 1;
    const int wr_c0  = (tid & 1) * 32;
    const bool wrow_ok = (jk0 + wr_row) < JK_TOTAL;

    float4 wreg[8];
    // LDG for i=0
    {
        const float4* src = (const float4*)(W1 + ((size_t)0 * JK_TOTAL + jk0 + wr_row) * 64 + wr_c0);
        #pragma unroll
        for (int q = 0; q < 8; ++q)
            wreg[q] = wrow_ok ? __ldg(src + q) : make_float4(0.f, 0.f, 0.f, 0.f);
    }
    // STS for i=0 into buf0
    {
        char* whi = smem + SM_WBUF;
        char* wlo = whi + W_BYTES;
        #pragma unroll
        for (int q = 0; q < 8; ++q) {
            float4 f = wreg[q];
            uint32_t h01, h23, l01, l23;
            CVT_BF16X2(h01, f.x, f.y);
            CVT_BF16X2(h23, f.z, f.w);
            float e0 = f.x - __uint_as_float(h01 << 16);
            float e1 = f.y - __uint_as_float(h01 & 0xFFFF0000u);
            float e2 = f.z - __uint_as_float(h23 << 16);
            float e3 = f.w - __uint_as_float(h23 & 0xFFFF0000u);
            CVT_BF16X2(l01, e0, e1);
            CVT_BF16X2(l23, e2, e3);
            uint32_t off = (uint32_t)(wr_row * W_STRIDE + wr_c0 + q * 4) * 2;
            *(uint2*)(whi + off) = make_uint2(h01, h23);
            *(uint2*)(wlo + off) = make_uint2(l01, l23);
        }
    }
    __syncthreads();

    // ---- ldmatrix address bases ----
    // A (G): row = warp*16 + (lane&7) + ((lane>>3)&1)*8 ; +16B for lanes 16-31
    const uint32_t a_row = (uint32_t)(warp * 16 + (lane & 7) + ((lane >> 3) & 1) * 8);
    const uint32_t a_off = a_row * (G_STRIDE * 2) + ((lane >> 4) & 1) * 16;
    const uint32_t ah_base = sb + SM_GHI + a_off;
    const uint32_t al_base = sb + SM_GLO + a_off;
    // B (W): row(k) = ks*16 + (lane&7) + ((lane>>3)&1)*8 ; col(h) = g*16 + ((lane>>4)&1)*8
    const uint32_t b_row = (uint32_t)((lane & 7) + ((lane >> 3) & 1) * 8);
    const uint32_t b_colb = ((lane >> 4) & 1) * 16;   // bytes

    // accumulators: 8 ntiles x 4
    float acc[8][4];
    #pragma unroll
    for (int nt = 0; nt < 8; ++nt)
        #pragma unroll
        for (int q = 0; q < 4; ++q) acc[nt][q] = 0.0f;

    const int arow0 = warp * 16 + (lane >> 2);   // rows for c0,c1 ; +8 for c2,c3

    for (int i = 0; i < NI; ++i) {
        // prefetch W[i+1]
        if (i + 1 < NI) {
            const float4* src = (const float4*)(W1 + ((size_t)(i + 1) * JK_TOTAL + jk0 + wr_row) * 64 + wr_c0);
            #pragma unroll
            for (int q = 0; q < 8; ++q)
                wreg[q] = wrow_ok ? __ldg(src + q) : make_float4(0.f, 0.f, 0.f, 0.f);
        }
        // prefetch a_h scalars
        float av0 = a_s[arow0 * 65 + i];
        float av1 = a_s[(arow0 + 8) * 65 + i];

        const uint32_t whb = sb + SM_WBUF + (uint32_t)(i & 1) * (2 * W_BYTES);
        const uint32_t wlb = whb + W_BYTES;

        float d[8][4];
        #pragma unroll
        for (int nt = 0; nt < 8; ++nt)
            #pragma unroll
            for (int q = 0; q < 4; ++q) d[nt][q] = 0.0f;

        #pragma unroll
        for (int ks = 0; ks < 8; ++ks) {
            uint32_t ah[4], al[4];
            LDSM4(ah, ah_base + (uint32_t)ks * 32);
            LDSM4(al, al_base + (uint32_t)ks * 32);
            uint32_t roff = ((uint32_t)ks * 16 + b_row) * (W_STRIDE * 2);
            uint32_t bh[4][4], bl[4][4];
            #pragma unroll
            for (int g = 0; g < 4; ++g)
                LDSM4T(bh[g], whb + roff + (uint32_t)g * 32 + b_colb);
            #pragma unroll
            for (int g = 0; g < 4; ++g)
                LDSM4T(bl[g], wlb + roff + (uint32_t)g * 32 + b_colb);
            #pragma unroll
            for (int nt = 0; nt < 8; ++nt) {
                const int g = nt >> 1, o = (nt & 1) * 2;
                MMA_BF16(d[nt], ah, bh[g][o], bh[g][o + 1]);
                MMA_BF16(d[nt], ah, bl[g][o], bl[g][o + 1]);
                MMA_BF16(d[nt], al, bh[g][o], bh[g][o + 1]);
            }
        }

        // scale by a_h and accumulate
        #pragma unroll
        for (int nt = 0; nt < 8; ++nt) {
            acc[nt][0] = fmaf(av0, d[nt][0], acc[nt][0]);
            acc[nt][1] = fmaf(av0, d[nt][1], acc[nt][1]);
            acc[nt][2] = fmaf(av1, d[nt][2], acc[nt][2]);
            acc[nt][3] = fmaf(av1, d[nt][3], acc[nt][3]);
        }

        // store W[i+1] into other buffer
        if (i + 1 < NI) {
            char* whi = smem + SM_WBUF + ((i + 1) & 1) * (2 * W_BYTES);
            char* wlo = whi + W_BYTES;
            #pragma unroll
            for (int q = 0; q < 8; ++q) {
                float4 f = wreg[q];
                uint32_t h01, h23, l01, l23;
                CVT_BF16X2(h01, f.x, f.y);
                CVT_BF16X2(h23, f.z, f.w);
                float e0 = f.x - __uint_as_float(h01 << 16);
                float e1 = f.y - __uint_as_float(h01 & 0xFFFF0000u);
                float e2 = f.z - __uint_as_float(h23 << 16);
                float e3 = f.w - __uint_as_float(h23 & 0xFFFF0000u);
                CVT_BF16X2(l01, e0, e1);
                CVT_BF16X2(l23, e2, e3);
                uint32_t off = (uint32_t)(wr_row * W_STRIDE + wr_c0 + q * 4) * 2;
                *(uint2*)(whi + off) = make_uint2(h01, h23);
                *(uint2*)(wlo + off) = make_uint2(l01, l23);
            }
        }
        __syncthreads();
    }

    // ---- write split partial ----
    {
        float* gp = g_partial + (size_t)blockIdx.y * (512 * 64) + (size_t)b0 * 64;
        const int c0 = (lane & 3) * 2;
        #pragma unroll
        for (int nt = 0; nt < 8; ++nt) {
            *(float2*)(gp + (size_t)arow0 * 64 + nt * 8 + c0)       = make_float2(acc[nt][0], acc[nt][1]);
            *(float2*)(gp + (size_t)(arow0 + 8) * 64 + nt * 8 + c0) = make_float2(acc[nt][2], acc[nt][3]);
        }
    }
}

// ---------- reduce: sum 34 partials + b1 + tanh -> g_h1 ----------
__global__ __launch_bounds__(256, 1)
void reduce_kernel(const float* __restrict__ b1) {
    int idx = blockIdx.x * 256 + threadIdx.x;    // 0..32767
    float s0 = 0.f, s1 = 0.f;
    #pragma unroll
    for (int r = 0; r < NSPLIT; r += 2) {
        s0 += g_partial[(size_t)r * 32768 + idx];
        s1 += g_partial[(size_t)(r + 1) * 32768 + idx];
    }
    g_h1[idx] = tanhf(s0 + s1 + b1[idx & 63]);
}

// ---------- MLP layers 2,3 ----------
__global__ __launch_bounds__(256, 1)
void mlp_kernel(const float* __restrict__ W2, const float* __restrict__ b2,
                const float* __restrict__ W3, const float* __restrict__ b3,
                float* __restrict__ out) {
    __shared__ __align__(16) float h_s[64 * 65];
    __shared__ __align__(16) float w_s[64 * 64];
    const int tid = threadIdx.x;
    const int bt  = blockIdx.x;      // 0..7

    for (int x = tid; x < 4096; x += 256)
        h_s[(x >> 6) * 65 + (x & 63)] = g_h1[bt * 4096 + x];
    for (int x = tid; x < 1024; x += 256)
        ((float4*)w_s)[x] = ((const float4*)W2)[x];
    __syncthreads();

    const int hg = tid & 7, bg = tid >> 3;
    const int h0 = hg * 8;
    float acc[2][8];

    #pragma unroll
    for (int bb = 0; bb < 2; ++bb)
        #pragma unroll
        for (int hh = 0; hh < 8; ++hh) acc[bb][hh] = 0.0f;
    #pragma unroll 4
    for (int k = 0; k < 64; ++k) {
        float hv0 = h_s[(bg * 2 + 0) * 65 + k];
        float hv1 = h_s[(bg * 2 + 1) * 65 + k];
        const float* wr = &w_s[k * 64 + h0];
        #pragma unroll
        for (int hh = 0; hh < 8; ++hh) {
            float wv = wr[hh];
            acc[0][hh] += hv0 * wv;
            acc[1][hh] += hv1 * wv;
        }
    }
    __syncthreads();
    #pragma unroll
    for (int bb = 0; bb < 2; ++bb)
        #pragma unroll
        for (int hh = 0; hh < 8; ++hh)
            h_s[(bg * 2 + bb) * 65 + h0 + hh] = tanhf(acc[bb][hh] + b2[h0 + hh]);
    for (int x = tid; x < 1024; x += 256)
        ((float4*)w_s)[x] = ((const float4*)W3)[x];
    __syncthreads();

    #pragma unroll
    for (int bb = 0; bb < 2; ++bb)
        #pragma unroll
        for (int hh = 0; hh < 8; ++hh) acc[bb][hh] = 0.0f;
    #pragma unroll 4
    for (int k = 0; k < 64; ++k) {
        float hv0 = h_s[(bg * 2 + 0) * 65 + k];
        float hv1 = h_s[(bg * 2 + 1) * 65 + k];
        const float* wr = &w_s[k * 64 + h0];
        #pragma unroll
        for (int hh = 0; hh < 8; ++hh) {
            float wv = wr[hh];
            acc[0][hh] += hv0 * wv;
            acc[1][hh] += hv1 * wv;
        }
    }
    #pragma unroll
    for (int bb = 0; bb < 2; ++bb) {
        int b = bt * 64 + bg * 2 + bb;
        float o[8];
        #pragma unroll
        for (int hh = 0; hh < 8; ++hh)
            o[hh] = tanhf(acc[bb][hh] + b3[h0 + hh]);
        *(float4*)(&out[b * 64 + h0])     = make_float4(o[0], o[1], o[2], o[3]);
        *(float4*)(&out[b * 64 + h0 + 4]) = make_float4(o[4], o[5], o[6], o[7]);
    }
}

extern "C" void kernel_launch(void* const* d_in, const int* in_sizes, int n_in,
                              void* d_out, int out_size) {
    (void)in_sizes; (void)n_in; (void)out_size;
    const float* l  = (const float*)d_in[0];
    const float* a  = (const float*)d_in[1];
    const float* v  = (const float*)d_in[2];
    const float* W1 = (const float*)d_in[3];
    const float* b1 = (const float*)d_in[4];
    const float* W2 = (const float*)d_in[5];
    const float* b2 = (const float*)d_in[6];
    const float* W3 = (const float*)d_in[7];
    const float* b3 = (const float*)d_in[8];
    float* out = (float*)d_out;

    cudaFuncSetAttribute(fusion_mma_kernel,
                         cudaFuncAttributeMaxDynamicSharedMemorySize, SMEM_TOTAL);
    dim3 grid1(4, NSPLIT);
    fusion_mma_kernel<<<grid1, 256, SMEM_TOTAL>>>(l, a, v, W1);
    reduce_kernel<<<128, 256>>>(b1);
    mlp_kernel<<<8, 256>>>(W2, b2, W3, b3, out);
}

// round 8
// speedup vs baseline: 5.0630x; 1.8533x over previous
#include <cuda_runtime.h>
#include <cuda_fp16.h>
#include <cstdint>
#include <cstddef>
#include <cstring>

// TensorFusion via mma.sync fp16 2-term split — compute_103-safe.
// out1[b,h] = sum_i a_h[b,i] * (G[b,:] @ W1_i),  G[b,jk] = v_h[b,j]*t_h[b,k]
// G = Gh + Gl (fp16 hi/lo); terms Gh*Wh + Gl*Wh (drop Gh*Wl ~2^-11 -> rel err ~1.5e-4).
// A (G) fragments REGISTER-RESIDENT across the whole i-loop (G is i-invariant).
// Grid 4 btiles x 67 jk-splits (KC=64) = 268 CTAs, 512 threads (16 warps: 8m x 2n).

#define NSPLIT 67
#define KC 64
#define JK_TOTAL 4225
#define NI 65

__device__ float g_partial[NSPLIT * 512 * 64];
__device__ float g_h1[512 * 64];

// ---------- helpers ----------
__device__ __forceinline__ uint32_t smem_u32(const void* p) {
    uint32_t r;
    asm("{ .reg .u64 t; cvta.to.shared.u64 t, %1; cvt.u32.u64 %0, t; }" : "=r"(r) : "l"(p));
    return r;
}
__device__ __forceinline__ uint32_t h2u(half2 h) {
    uint32_t u;
    memcpy(&u, &h, 4);
    return u;
}
#define LDSM4(R, ADDR) \
    asm volatile("ldmatrix.sync.aligned.m8n8.x4.shared.b16 {%0,%1,%2,%3}, [%4];" \
                 : "=r"((R)[0]), "=r"((R)[1]), "=r"((R)[2]), "=r"((R)[3]) : "r"(ADDR))
#define LDSM4T(R, ADDR) \
    asm volatile("ldmatrix.sync.aligned.m8n8.x4.trans.shared.b16 {%0,%1,%2,%3}, [%4];" \
                 : "=r"((R)[0]), "=r"((R)[1]), "=r"((R)[2]), "=r"((R)[3]) : "r"(ADDR))
#define MMA_F16(D, A, B0, B1) \
    asm volatile("mma.sync.aligned.m16n8k16.row.col.f32.f16.f16.f32 " \
                 "{%0,%1,%2,%3}, {%4,%5,%6,%7}, {%8,%9}, {%0,%1,%2,%3};" \
                 : "+f"((D)[0]), "+f"((D)[1]), "+f"((D)[2]), "+f"((D)[3]) \
                 : "r"((A)[0]), "r"((A)[1]), "r"((A)[2]), "r"((A)[3]), "r"(B0), "r"(B1))

// ---------- smem layout ----------
// W bufs (fp16 hi only): 2 x [64 rows(k)][72 cols(h)]  stride 144B (conflict-free)
// G tiles hi/lo:             [128 rows(b)][72 cols(jk)] stride 144B
// a_s: [128][65] f32
#define W_STRIDE 72
#define W_BYTES  (64 * W_STRIDE * 2)            // 9216
#define SM_WBUF  0                              // 2 bufs -> 18432
#define G_STRIDE 72
#define SM_GHI   (2 * W_BYTES)                  // 18432
#define SM_GLO   (SM_GHI + 128 * G_STRIDE * 2)  // +18432 = 36864
#define SM_AS    (SM_GLO + 128 * G_STRIDE * 2)  // 55296
#define SMEM_TOTAL (SM_AS + 128 * 65 * 4)       // 88576

__global__ __launch_bounds__(512, 1)
void fusion_mma_kernel(const float* __restrict__ l, const float* __restrict__ a,
                       const float* __restrict__ v, const float* __restrict__ W1) {
    extern __shared__ __align__(1024) char smem[];
    const uint32_t sb = smem_u32(smem);
    const int tid  = threadIdx.x;
    const int warp = tid >> 5;
    const int lane = tid & 31;
    const int mw   = warp & 7;       // m-tile 0..7
    const int nh   = warp >> 3;      // n-half 0..1
    const int b0   = blockIdx.x * 128;
    const int jk0  = blockIdx.y * KC;

    float* a_s = (float*)(smem + SM_AS);

    // ---- stage a_s[128][65] ----
    for (int x = tid; x < 128 * 65; x += 512) {
        int r = x / 65, i = x - r * 65;
        a_s[x] = (i == 0) ? 1.0f : __ldg(&a[(b0 + r) * 64 + (i - 1)]);
    }

    // ---- build G tile [128][64] fp16 hi/lo ----
    {
        int r  = tid >> 2;
        int c0 = (tid & 3) * 16;
        const float* lrow = l + (size_t)(b0 + r) * 64;
        const float* vrow = v + (size_t)(b0 + r) * 64;
        int jk = jk0 + c0;
        int j  = jk / 65, k = jk - j * 65;
        char* gh = smem + SM_GHI + (size_t)(r * G_STRIDE + c0) * 2;
        char* gl = smem + SM_GLO + (size_t)(r * G_STRIDE + c0) * 2;
        #pragma unroll
        for (int c = 0; c < 16; c += 2) {
            float g0 = 0.0f, g1 = 0.0f;
            if (jk < JK_TOTAL)
                g0 = (j ? __ldg(&vrow[j - 1]) : 1.0f) * (k ? __ldg(&lrow[k - 1]) : 1.0f);
            ++jk; if (++k == 65) { k = 0; ++j; }
            if (jk < JK_TOTAL)
                g1 = (j ? __ldg(&vrow[j - 1]) : 1.0f) * (k ? __ldg(&lrow[k - 1]) : 1.0f);
            ++jk; if (++k == 65) { k = 0; ++j; }
            half2 hp = __floats2half2_rn(g0, g1);
            float2 hf = __half22float2(hp);
            half2 lp = __floats2half2_rn(g0 - hf.x, g1 - hf.y);
            *(half2*)(gh + c * 2) = hp;
            *(half2*)(gl + c * 2) = lp;
        }
    }

    // ---- W staging mapping: thread t -> row t>>3 (k), cols (t&7)*8..+8 ----
    const int wr_row = tid >> 3;                 // 0..63
    const int wr_c0  = (tid & 7) * 8;
    const bool wrow_ok = (jk0 + wr_row) < JK_TOTAL;

    float4 wreg[2];
    {   // LDG W for i=0
        const float4* src = (const float4*)(W1 + ((size_t)0 * JK_TOTAL + jk0 + wr_row) * 64 + wr_c0);
        wreg[0] = wrow_ok ? __ldg(src)     : make_float4(0.f, 0.f, 0.f, 0.f);
        wreg[1] = wrow_ok ? __ldg(src + 1) : make_float4(0.f, 0.f, 0.f, 0.f);
    }
    {   // STS W i=0 into buf0 (fp16 hi)
        uint4 pk;
        pk.x = h2u(__floats2half2_rn(wreg[0].x, wreg[0].y));
        pk.y = h2u(__floats2half2_rn(wreg[0].z, wreg[0].w));
        pk.z = h2u(__floats2half2_rn(wreg[1].x, wreg[1].y));
        pk.w = h2u(__floats2half2_rn(wreg[1].z, wreg[1].w));
        *(uint4*)(smem + SM_WBUF + (size_t)(wr_row * W_STRIDE + wr_c0) * 2) = pk;
    }
    __syncthreads();

    // ---- preload A (G) fragments into registers: i-invariant! ----
    uint32_t AH[4][4], AL[4][4];
    {
        const uint32_t a_row = (uint32_t)(mw * 16 + (lane & 7) + ((lane >> 3) & 1) * 8);
        const uint32_t a_off = a_row * (G_STRIDE * 2) + ((lane >> 4) & 1) * 16;
        #pragma unroll
        for (int ks = 0; ks < 4; ++ks) {
            LDSM4(AH[ks], sb + SM_GHI + a_off + (uint32_t)ks * 32);
            LDSM4(AL[ks], sb + SM_GLO + a_off + (uint32_t)ks * 32);
        }
    }

    // B address components
    const uint32_t b_row  = (uint32_t)((lane & 7) + ((lane >> 3) & 1) * 8);
    const uint32_t b_colb = (uint32_t)(nh * 64 + ((lane >> 4) & 1) * 16);  // bytes

    float acc[4][4];
    #pragma unroll
    for (int nt = 0; nt < 4; ++nt)
        #pragma unroll
        for (int q = 0; q < 4; ++q) acc[nt][q] = 0.0f;

    const int arow0 = mw * 16 + (lane >> 2);

    for (int i = 0; i < NI; ++i) {
        // prefetch W[i+1]
        if (i + 1 < NI) {
            const float4* src = (const float4*)(W1 + ((size_t)(i + 1) * JK_TOTAL + jk0 + wr_row) * 64 + wr_c0);
            wreg[0] = wrow_ok ? __ldg(src)     : make_float4(0.f, 0.f, 0.f, 0.f);
            wreg[1] = wrow_ok ? __ldg(src + 1) : make_float4(0.f, 0.f, 0.f, 0.f);
        }
        float av0 = a_s[arow0 * 65 + i];
        float av1 = a_s[(arow0 + 8) * 65 + i];

        const uint32_t wb = sb + SM_WBUF + (uint32_t)(i & 1) * W_BYTES;

        float d[4][4];
        #pragma unroll
        for (int nt = 0; nt < 4; ++nt)
            #pragma unroll
            for (int q = 0; q < 4; ++q) d[nt][q] = 0.0f;

        #pragma unroll
        for (int ks = 0; ks < 4; ++ks) {
            uint32_t bh[2][4];
            uint32_t roff = ((uint32_t)ks * 16 + b_row) * (W_STRIDE * 2);
            LDSM4T(bh[0], wb + roff + b_colb);
            LDSM4T(bh[1], wb + roff + 32 + b_colb);
            #pragma unroll
            for (int nt = 0; nt < 4; ++nt) {
                const int g = nt >> 1, o = (nt & 1) * 2;
                MMA_F16(d[nt], AH[ks], bh[g][o], bh[g][o + 1]);
                MMA_F16(d[nt], AL[ks], bh[g][o], bh[g][o + 1]);
            }
        }

        // scale by a_h and accumulate
        #pragma unroll
        for (int nt = 0; nt < 4; ++nt) {
            acc[nt][0] = fmaf(av0, d[nt][0], acc[nt][0]);
            acc[nt][1] = fmaf(av0, d[nt][1], acc[nt][1]);
            acc[nt][2] = fmaf(av1, d[nt][2], acc[nt][2]);
            acc[nt][3] = fmaf(av1, d[nt][3], acc[nt][3]);
        }

        // store W[i+1] into other buffer
        if (i + 1 < NI) {
            uint4 pk;
            pk.x = h2u(__floats2half2_rn(wreg[0].x, wreg[0].y));
            pk.y = h2u(__floats2half2_rn(wreg[0].z, wreg[0].w));
            pk.z = h2u(__floats2half2_rn(wreg[1].x, wreg[1].y));
            pk.w = h2u(__floats2half2_rn(wreg[1].z, wreg[1].w));
            *(uint4*)(smem + SM_WBUF + (size_t)((i + 1) & 1) * W_BYTES
                      + (size_t)(wr_row * W_STRIDE + wr_c0) * 2) = pk;
        }
        __syncthreads();
    }

    // ---- write split partial ----
    {
        float* gp = g_partial + (size_t)blockIdx.y * (512 * 64) + (size_t)b0 * 64;
        const int c0 = nh * 32 + (lane & 3) * 2;
        #pragma unroll
        for (int nt = 0; nt < 4; ++nt) {
            *(float2*)(gp + (size_t)arow0 * 64 + nt * 8 + c0)       = make_float2(acc[nt][0], acc[nt][1]);
            *(float2*)(gp + (size_t)(arow0 + 8) * 64 + nt * 8 + c0) = make_float2(acc[nt][2], acc[nt][3]);
        }
    }
}

// ---------- reduce: sum 67 partials + b1 + tanh -> g_h1 ----------
__global__ __launch_bounds__(256, 1)
void reduce_kernel(const float* __restrict__ b1) {
    int idx = blockIdx.x * 256 + threadIdx.x;    // 0..32767
    float s0 = 0.f, s1 = 0.f;
    #pragma unroll
    for (int r = 0; r + 1 < NSPLIT; r += 2) {
        s0 += g_partial[(size_t)r * 32768 + idx];
        s1 += g_partial[(size_t)(r + 1) * 32768 + idx];
    }
    s0 += g_partial[(size_t)(NSPLIT - 1) * 32768 + idx];
    g_h1[idx] = tanhf(s0 + s1 + b1[idx & 63]);
}

// ---------- MLP layers 2,3 ----------
__global__ __launch_bounds__(256, 1)
void mlp_kernel(const float* __restrict__ W2, const float* __restrict__ b2,
                const float* __restrict__ W3, const float* __restrict__ b3,
                float* __restrict__ out) {
    __shared__ __align__(16) float h_s[64 * 65];
    __shared__ __align__(16) float w_s[64 * 64];
    const int tid = threadIdx.x;
    const int bt  = blockIdx.x;      // 0..7

    for (int x = tid; x < 4096; x += 256)
        h_s[(x >> 6) * 65 + (x & 63)] = g_h1[bt * 4096 + x];
    for (int x = tid; x < 1024; x += 256)
        ((float4*)w_s)[x] = ((const float4*)W2)[x];
    __syncthreads();

    const int hg = tid & 7, bg = tid >> 3;
    const int h0 = hg * 8;
    float acc[2][8];

    #pragma unroll
    for (int bb = 0; bb < 2; ++bb)
        #pragma unroll
        for (int hh = 0; hh < 8; ++hh) acc[bb][hh] = 0.0f;
    #pragma unroll 4
    for (int k = 0; k < 64; ++k) {
        float hv0 = h_s[(bg * 2 + 0) * 65 + k];
        float hv1 = h_s[(bg * 2 + 1) * 65 + k];
        const float* wr = &w_s[k * 64 + h0];
        #pragma unroll
        for (int hh = 0; hh < 8; ++hh) {
            float wv = wr[hh];
            acc[0][hh] += hv0 * wv;
            acc[1][hh] += hv1 * wv;
        }
    }
    __syncthreads();
    #pragma unroll
    for (int bb = 0; bb < 2; ++bb)
        #pragma unroll
        for (int hh = 0; hh < 8; ++hh)
            h_s[(bg * 2 + bb) * 65 + h0 + hh] = tanhf(acc[bb][hh] + b2[h0 + hh]);
    for (int x = tid; x < 1024; x += 256)
        ((float4*)w_s)[x] = ((const float4*)W3)[x];
    __syncthreads();

    #pragma unroll
    for (int bb = 0; bb < 2; ++bb)
        #pragma unroll
        for (int hh = 0; hh < 8; ++hh) acc[bb][hh] = 0.0f;
    #pragma unroll 4
    for (int k = 0; k < 64; ++k) {
        float hv0 = h_s[(bg * 2 + 0) * 65 + k];
        float hv1 = h_s[(bg * 2 + 1) * 65 + k];
        const float* wr = &w_s[k * 64 + h0];
        #pragma unroll
        for (int hh = 0; hh < 8; ++hh) {
            float wv = wr[hh];
            acc[0][hh] += hv0 * wv;
            acc[1][hh] += hv1 * wv;
        }
    }
    #pragma unroll
    for (int bb = 0; bb < 2; ++bb) {
        int b = bt * 64 + bg * 2 + bb;
        float o[8];
        #pragma unroll
        for (int hh = 0; hh < 8; ++hh)
            o[hh] = tanhf(acc[bb][hh] + b3[h0 + hh]);
        *(float4*)(&out[b * 64 + h0])     = make_float4(o[0], o[1], o[2], o[3]);
        *(float4*)(&out[b * 64 + h0 + 4]) = make_float4(o[4], o[5], o[6], o[7]);
    }
}

extern "C" void kernel_launch(void* const* d_in, const int* in_sizes, int n_in,
                              void* d_out, int out_size) {
    (void)in_sizes; (void)n_in; (void)out_size;
    const float* l  = (const float*)d_in[0];
    const float* a  = (const float*)d_in[1];
    const float* v  = (const float*)d_in[2];
    const float* W1 = (const float*)d_in[3];
    const float* b1 = (const float*)d_in[4];
    const float* W2 = (const float*)d_in[5];
    const float* b2 = (const float*)d_in[6];
    const float* W3 = (const float*)d_in[7];
    const float* b3 = (const float*)d_in[8];
    float* out = (float*)d_out;

    cudaFuncSetAttribute(fusion_mma_kernel,
                         cudaFuncAttributeMaxDynamicSharedMemorySize, SMEM_TOTAL);
    dim3 grid1(4, NSPLIT);
    fusion_mma_kernel<<<grid1, 512, SMEM_TOTAL>>>(l, a, v, W1);
    reduce_kernel<<<128, 256>>>(b1);
    mlp_kernel<<<8, 256>>>(W2, b2, W3, b3, out);
}